// round 5
// baseline (speedup 1.0000x reference)
#include <cuda_runtime.h>
#include <cstdint>

#define HH  1024
#define BB  2
#define SS  2048
#define NHH 16
#define HDD 64
#define MT  (BB*SS)   // 4096

// ---------------- scratch globals (allocation-free) ----------------
__device__ __align__(128) float g_xhi[MT*HH];     // tf32(x), k-packed
__device__ __align__(128) float g_xlo[MT*HH];     // tf32(x - hi), k-packed
__device__ __align__(128) float g_WdThi[HH*HH];   // (Wq-Wk)^T hi, k-packed
__device__ __align__(128) float g_WdTlo[HH*HH];
__device__ __align__(128) float g_WvT[HH*HH];     // Wv^T, k-packed
__device__ __align__(128) float g_WoT[HH*HH];     // Wo^T, k-packed
__device__ __align__(128) float g_bd[HH];
__device__ __align__(128) float g_Dhi[MT*HH];     // tf32(D), d-packed per head
__device__ __align__(128) float g_Dlo[MT*HH];
__device__ __align__(128) float g_Vt[MT*HH];      // V^T per head: [b][h][d][p(s)]
__device__ __align__(128) float g_C[MT*HH];       // ctx, packed per head (O-GEMM k)

// ---------------- helpers ----------------
__device__ __forceinline__ int p8(int e) { return ((e & 3) << 1) | (e >> 2); }
__device__ __forceinline__ int pk(int k) { return (k & ~7) | p8(k & 7); }
__device__ __forceinline__ float tfr(float x) {
    uint32_t r;
    asm("cvt.rna.tf32.f32 %0, %1;" : "=r"(r) : "f"(x));
    return __uint_as_float(r);
}
__device__ __forceinline__ void cp16(float* s, const float* g) {
    uint32_t sa = (uint32_t)__cvta_generic_to_shared(s);
    asm volatile("cp.async.cg.shared.global [%0], [%1], 16;" :: "r"(sa), "l"(g));
}
__device__ __forceinline__ void cp_commit() { asm volatile("cp.async.commit_group;"); }
template<int N> __device__ __forceinline__ void cp_wait() {
    asm volatile("cp.async.wait_group %0;" :: "n"(N));
}
__device__ __forceinline__ void mma8(float* d, const uint32_t* a, uint32_t b0, uint32_t b1) {
    asm volatile(
        "mma.sync.aligned.m16n8k8.row.col.f32.tf32.tf32.f32 "
        "{%0,%1,%2,%3},{%4,%5,%6,%7},{%8,%9},{%0,%1,%2,%3};"
        : "+f"(d[0]), "+f"(d[1]), "+f"(d[2]), "+f"(d[3])
        : "r"(a[0]), "r"(a[1]), "r"(a[2]), "r"(a[3]), "r"(b0), "r"(b1));
}

// ---------------- prep: x -> hi/lo planes (k-packed); bd = bq-bk ----------------
__global__ void prep_x(const float* __restrict__ x,
                       const float* __restrict__ bq, const float* __restrict__ bk) {
    int i = blockIdx.x * 256 + threadIdx.x;
    float v = x[i];
    float hi = tfr(v);
    int o = (i & ~7) | p8(i & 7);
    g_xhi[o] = hi;
    g_xlo[o] = tfr(v - hi);
    if (i < HH) g_bd[i] = bq[i] - bk[i];
}

// ---------------- prep: transpose + tf32 + k-pack weights ----------------
__global__ void prep_w(const float* __restrict__ Wq, const float* __restrict__ Wk,
                       const float* __restrict__ Wv, const float* __restrict__ Wo) {
    __shared__ float t0[32][33];
    __shared__ float t1[32][33];
    const int z = blockIdx.z;
    const int c0 = blockIdx.x * 32, r0 = blockIdx.y * 32;
    const int tx = threadIdx.x & 31, ty = threadIdx.x >> 5;
    #pragma unroll
    for (int rr = ty; rr < 32; rr += 8) {
        int idx = (r0 + rr) * HH + c0 + tx;
        if (z == 0) {
            float v = Wq[idx] - Wk[idx];
            float hi = tfr(v);
            t0[rr][tx] = hi;
            t1[rr][tx] = tfr(v - hi);
        } else if (z == 1) t0[rr][tx] = tfr(Wv[idx]);
        else               t0[rr][tx] = tfr(Wo[idx]);
    }
    __syncthreads();
    #pragma unroll
    for (int rr = ty; rr < 32; rr += 8) {
        int odx = (c0 + rr) * HH + r0 + pk(tx);   // transposed, k packed
        if (z == 0) { g_WdThi[odx] = t0[tx][rr]; g_WdTlo[odx] = t1[tx][rr]; }
        else if (z == 1) g_WvT[odx] = t0[tx][rr];
        else             g_WoT[odx] = t0[tx][rr];
    }
}

// ---------------- tf32 GEMM (plain): acc = A @ BT^T ----------------
// MODE 0: out = acc + bias (fp32, final).  MODE 1: V^T packed store, tf32-rounded.
#define GP 12
template<int MODE>
__global__ __launch_bounds__(256, 2) void gemm_plain(
    const float* __restrict__ A, const float* __restrict__ BT,
    const float* __restrict__ bias, float* __restrict__ C)
{
    extern __shared__ float sm[];
    const int K = HH, N = HH;
    const int tid = threadIdx.x, w = tid >> 5, lane = tid & 31;
    const int g = lane >> 2, t = lane & 3;
    const int wm = (w & 3) * 32, wn = (w >> 2) * 64;
    const int rowBase = blockIdx.y * 128, colBase = blockIdx.x * 128;
    const int lr = tid >> 1, lc = (tid & 1) * 4;

    const float* pA = A  + (size_t)(rowBase + lr) * K + lc;
    const float* pB = BT + (size_t)(colBase + lr) * K + lc;

    float acc[2][8][4];
    #pragma unroll
    for (int mt = 0; mt < 2; mt++)
        #pragma unroll
        for (int nt = 0; nt < 8; nt++)
            #pragma unroll
            for (int q = 0; q < 4; q++) acc[mt][nt][q] = 0.f;

    const int NIT = K / 8;
    const int off = lr * GP + lc;
    auto issue = [&](int it, int s) {
        float* base = sm + s * 2 * 128 * GP;
        cp16(base + off,          pA + it * 8);
        cp16(base + 128*GP + off, pB + it * 8);
    };
    issue(0, 0); cp_commit();
    issue(1, 1); cp_commit();

    for (int i = 0; i < NIT; i++) {
        cp_wait<1>();
        __syncthreads();
        const float* base = sm + (i % 3) * 2 * 128 * GP;
        const float* sA = base;
        const float* sB = base + 128 * GP;
        uint32_t a[2][4];
        #pragma unroll
        for (int mt = 0; mt < 2; mt++) {
            int r = wm + mt * 16 + g;
            float2 v0 = *(const float2*)&sA[r * GP + 2*t];
            float2 v1 = *(const float2*)&sA[(r + 8) * GP + 2*t];
            a[mt][0] = __float_as_uint(v0.x); a[mt][2] = __float_as_uint(v0.y);
            a[mt][1] = __float_as_uint(v1.x); a[mt][3] = __float_as_uint(v1.y);
        }
        #pragma unroll
        for (int nt = 0; nt < 8; nt++) {
            int c = wn + nt * 8 + g;
            float2 bv = *(const float2*)&sB[c * GP + 2*t];
            uint32_t b0 = __float_as_uint(bv.x), b1 = __float_as_uint(bv.y);
            mma8(acc[0][nt], a[0], b0, b1);
            mma8(acc[1][nt], a[1], b0, b1);
        }
        if (i + 2 < NIT) issue(i + 2, (i + 2) % 3);
        cp_commit();
    }

    #pragma unroll
    for (int mt = 0; mt < 2; mt++)
        #pragma unroll
        for (int nt = 0; nt < 8; nt++) {
            int row = rowBase + wm + mt * 16 + g;
            int col = colBase + wn + nt * 8 + 2 * t;
            float2 bb = *(const float2*)(bias + col);
            float v00 = acc[mt][nt][0] + bb.x, v01 = acc[mt][nt][1] + bb.y;
            float v10 = acc[mt][nt][2] + bb.x, v11 = acc[mt][nt][3] + bb.y;
            if (MODE == 0) {
                *(float2*)(C + (size_t)row * N + col)       = make_float2(v00, v01);
                *(float2*)(C + (size_t)(row + 8) * N + col) = make_float2(v10, v11);
            } else {
                // V^T packed: [b][head][dd][p(s)]
                int b_ = row >> 11, s_ = row & 2047;
                int head = col >> 6, dd = col & 63;
                int ps = (s_ & ~7) | p8(s_ & 7);
                size_t r0 = ((size_t)((b_ * NHH + head) * HDD + dd)) * SS;
                size_t r1 = ((size_t)((b_ * NHH + head) * HDD + dd + 1)) * SS;
                C[r0 + ps]     = tfr(v00);
                C[r1 + ps]     = tfr(v01);
                C[r0 + ps + 8] = tfr(v10);
                C[r1 + ps + 8] = tfr(v11);
            }
        }
}

// ---------------- tf32x2 split GEMM for D; writes hi/lo planes (d-packed) ----------------
__global__ __launch_bounds__(256, 2) void gemm_split(
    const float* __restrict__ Ah, const float* __restrict__ Al,
    const float* __restrict__ Bh, const float* __restrict__ Bl,
    const float* __restrict__ bias,
    float* __restrict__ Chi, float* __restrict__ Clo)
{
    extern __shared__ float sm[];
    const int K = HH, N = HH;
    const int tid = threadIdx.x, w = tid >> 5, lane = tid & 31;
    const int g = lane >> 2, t = lane & 3;
    const int wm = (w & 3) * 32, wn = (w >> 2) * 64;
    const int rowBase = blockIdx.y * 128, colBase = blockIdx.x * 128;
    const int lr = tid >> 1, lc = (tid & 1) * 4;

    const float* pAh = Ah + (size_t)(rowBase + lr) * K + lc;
    const float* pAl = Al + (size_t)(rowBase + lr) * K + lc;
    const float* pBh = Bh + (size_t)(colBase + lr) * K + lc;
    const float* pBl = Bl + (size_t)(colBase + lr) * K + lc;

    float acc[2][8][4];
    #pragma unroll
    for (int mt = 0; mt < 2; mt++)
        #pragma unroll
        for (int nt = 0; nt < 8; nt++)
            #pragma unroll
            for (int q = 0; q < 4; q++) acc[mt][nt][q] = 0.f;

    const int NIT = K / 8;
    const int off = lr * GP + lc;
    auto issue = [&](int it, int s) {
        float* base = sm + s * 4 * 128 * GP;
        cp16(base + off,            pAh + it * 8);
        cp16(base + 128*GP   + off, pAl + it * 8);
        cp16(base + 2*128*GP + off, pBh + it * 8);
        cp16(base + 3*128*GP + off, pBl + it * 8);
    };
    issue(0, 0); cp_commit();
    issue(1, 1); cp_commit();

    for (int i = 0; i < NIT; i++) {
        cp_wait<1>();
        __syncthreads();
        const float* base = sm + (i % 3) * 4 * 128 * GP;
        const float* sAh = base;
        const float* sAl = base + 128 * GP;
        const float* sBh = base + 2 * 128 * GP;
        const float* sBl = base + 3 * 128 * GP;
        uint32_t ah[2][4], al[2][4];
        #pragma unroll
        for (int mt = 0; mt < 2; mt++) {
            int r = wm + mt * 16 + g;
            float2 v0 = *(const float2*)&sAh[r * GP + 2*t];
            float2 v1 = *(const float2*)&sAh[(r + 8) * GP + 2*t];
            ah[mt][0] = __float_as_uint(v0.x); ah[mt][2] = __float_as_uint(v0.y);
            ah[mt][1] = __float_as_uint(v1.x); ah[mt][3] = __float_as_uint(v1.y);
            float2 w0 = *(const float2*)&sAl[r * GP + 2*t];
            float2 w1 = *(const float2*)&sAl[(r + 8) * GP + 2*t];
            al[mt][0] = __float_as_uint(w0.x); al[mt][2] = __float_as_uint(w0.y);
            al[mt][1] = __float_as_uint(w1.x); al[mt][3] = __float_as_uint(w1.y);
        }
        #pragma unroll
        for (int nt = 0; nt < 8; nt++) {
            int c = wn + nt * 8 + g;
            float2 bh = *(const float2*)&sBh[c * GP + 2*t];
            float2 bl = *(const float2*)&sBl[c * GP + 2*t];
            uint32_t bh0 = __float_as_uint(bh.x), bh1 = __float_as_uint(bh.y);
            uint32_t bl0 = __float_as_uint(bl.x), bl1 = __float_as_uint(bl.y);
            #pragma unroll
            for (int mt = 0; mt < 2; mt++) {
                mma8(acc[mt][nt], ah[mt], bh0, bh1);
                mma8(acc[mt][nt], ah[mt], bl0, bl1);
                mma8(acc[mt][nt], al[mt], bh0, bh1);
            }
        }
        if (i + 2 < NIT) issue(i + 2, (i + 2) % 3);
        cp_commit();
    }

    const int sl0 = p8(2 * t), sl1 = p8(2 * t + 1);
    #pragma unroll
    for (int mt = 0; mt < 2; mt++)
        #pragma unroll
        for (int nt = 0; nt < 8; nt++) {
            int row = rowBase + wm + mt * 16 + g;
            int col = colBase + wn + nt * 8 + 2 * t;
            int cb  = colBase + wn + nt * 8;
            float2 bb = *(const float2*)(bias + col);
            float v00 = acc[mt][nt][0] + bb.x, v01 = acc[mt][nt][1] + bb.y;
            float v10 = acc[mt][nt][2] + bb.x, v11 = acc[mt][nt][3] + bb.y;
            float h00 = tfr(v00), h01 = tfr(v01), h10 = tfr(v10), h11 = tfr(v11);
            size_t r0 = (size_t)row * N, r1 = (size_t)(row + 8) * N;
            Chi[r0 + cb + sl0] = h00;  Chi[r0 + cb + sl1] = h01;
            Chi[r1 + cb + sl0] = h10;  Chi[r1 + cb + sl1] = h11;
            Clo[r0 + cb + sl0] = tfr(v00 - h00);  Clo[r0 + cb + sl1] = tfr(v01 - h01);
            Clo[r1 + cb + sl0] = tfr(v10 - h10);  Clo[r1 + cb + sl1] = tfr(v11 - h11);
        }
}

// ---------------- attention (tensor-core, packed vectorized operands) ----------------
#define SP 72
#define ASTG (3*64*SP)    // floats per stage: 13824
__global__ __launch_bounds__(256, 2) void attn_mma() {
    extern __shared__ float sm[];
    const int tid = threadIdx.x, w = tid >> 5, lane = tid & 31;
    const int g = lane >> 2, t = lane & 3;
    const int mrow = (w & 3) * 16, nhalf = (w >> 2) * 32;
    const int qt = blockIdx.x, bh = blockIdx.y;
    const int b = bh >> 4, h = bh & 15, q0 = qt * 64;

    const size_t base = (size_t)b * SS * HH + h * HDD;
    const float* Dh = g_Dhi + base;
    const float* Dl = g_Dlo + base;
    const float* Vt = g_Vt + (size_t)(b * NHH + h) * HDD * SS;

    // Dq fragments (hi/lo) in registers for the whole j-loop (pairs are adjacent)
    uint32_t qhi[8][4], qlo[8][4];
    {
        const size_t r0g = (size_t)(q0 + mrow + g) * HH;
        const size_t r1g = (size_t)(q0 + mrow + g + 8) * HH;
        #pragma unroll
        for (int c = 0; c < 8; c++) {
            int o = c * 8 + 2 * t;
            float2 h0 = *(const float2*)&Dh[r0g + o];
            float2 h1 = *(const float2*)&Dh[r1g + o];
            qhi[c][0] = __float_as_uint(h0.x); qhi[c][2] = __float_as_uint(h0.y);
            qhi[c][1] = __float_as_uint(h1.x); qhi[c][3] = __float_as_uint(h1.y);
            float2 l0 = *(const float2*)&Dl[r0g + o];
            float2 l1 = *(const float2*)&Dl[r1g + o];
            qlo[c][0] = __float_as_uint(l0.x); qlo[c][2] = __float_as_uint(l0.y);
            qlo[c][1] = __float_as_uint(l1.x); qlo[c][3] = __float_as_uint(l1.y);
        }
    }

    float oacc[4][4];
    #pragma unroll
    for (int i = 0; i < 4; i++)
        #pragma unroll
        for (int j = 0; j < 4; j++) oacc[i][j] = 0.f;

    const int lr = tid >> 2, lc = (tid & 3) * 16;
    auto issue = [&](int jt, int s) {
        float* st = sm + s * ASTG;
        const float* srcH = Dh + (size_t)(jt * 64 + lr) * HH + lc;
        const float* srcL = Dl + (size_t)(jt * 64 + lr) * HH + lc;
        const float* srcV = Vt + (size_t)lr * SS + jt * 64 + lc;
        #pragma unroll
        for (int u = 0; u < 16; u += 4) {
            cp16(st + lr * SP + lc + u,           srcH + u);
            cp16(st + 64*SP + lr * SP + lc + u,   srcL + u);
            cp16(st + 2*64*SP + lr * SP + lc + u, srcV + u);
        }
    };

    const int sl0 = p8(2 * t), sl1 = p8(2 * t + 1);
    int buf = 0;
    issue(qt, 0); cp_commit();
    for (int jt = qt; jt < SS / 64; jt++) {
        if (jt + 1 < SS / 64) { issue(jt + 1, buf ^ 1); cp_commit(); cp_wait<1>(); }
        else cp_wait<0>();
        __syncthreads();
        float* st = sm + buf * ASTG;
        float* sKh = st;                        // reused as S after score
        const float* sKl = st + 64 * SP;
        const float* sV  = st + 2 * 64 * SP;
        const int j0 = jt * 64;

        // score = Dq@Dk^T (3-mma tf32x2), all B-frag loads are LDS.64
        float sacc[4][4];
        #pragma unroll
        for (int i = 0; i < 4; i++)
            #pragma unroll
            for (int j = 0; j < 4; j++) sacc[i][j] = 0.f;

        #pragma unroll
        for (int c = 0; c < 8; c++) {
            int o = c * 8 + 2 * t;
            #pragma unroll
            for (int nt = 0; nt < 4; nt++) {
                int jr = (nhalf + nt * 8 + g) * SP;
                float2 bh = *(const float2*)&sKh[jr + o];
                float2 bl = *(const float2*)&sKl[jr + o];
                uint32_t bh0 = __float_as_uint(bh.x), bh1 = __float_as_uint(bh.y);
                uint32_t bl0 = __float_as_uint(bl.x), bl1 = __float_as_uint(bl.y);
                mma8(sacc[nt], qhi[c], bh0, bh1);
                mma8(sacc[nt], qhi[c], bl0, bl1);
                mma8(sacc[nt], qlo[c], bh0, bh1);
            }
        }

        // mask (strict upper) + exp + pre-round
        const int r0 = q0 + mrow + g;
        #pragma unroll
        for (int nt = 0; nt < 4; nt++) {
            int colb = j0 + nhalf + nt * 8 + 2 * t;
            sacc[nt][0] = (colb     > r0    ) ? tfr(__expf(-0.5f * sacc[nt][0])) : 0.f;
            sacc[nt][1] = (colb + 1 > r0    ) ? tfr(__expf(-0.5f * sacc[nt][1])) : 0.f;
            sacc[nt][2] = (colb     > r0 + 8) ? tfr(__expf(-0.5f * sacc[nt][2])) : 0.f;
            sacc[nt][3] = (colb + 1 > r0 + 8) ? tfr(__expf(-0.5f * sacc[nt][3])) : 0.f;
        }

        __syncthreads();   // all score reads of sKh/sKl done
        // store S packed (slots p8) so PV A-frag reload is LDS.64
        #pragma unroll
        for (int nt = 0; nt < 4; nt++) {
            int cb = nhalf + nt * 8;
            sKh[(mrow + g) * SP + cb + sl0]     = sacc[nt][0];
            sKh[(mrow + g) * SP + cb + sl1]     = sacc[nt][1];
            sKh[(mrow + g + 8) * SP + cb + sl0] = sacc[nt][2];
            sKh[(mrow + g + 8) * SP + cb + sl1] = sacc[nt][3];
        }
        __syncthreads();

        // PV: oacc += S @ V  (plain tf32), vectorized frags
        #pragma unroll
        for (int c = 0; c < 8; c++) {
            int o = c * 8 + 2 * t;
            float2 a01 = *(const float2*)&sKh[(mrow + g) * SP + o];
            float2 a23 = *(const float2*)&sKh[(mrow + g + 8) * SP + o];
            uint32_t a[4];
            a[0] = __float_as_uint(a01.x); a[2] = __float_as_uint(a01.y);
            a[1] = __float_as_uint(a23.x); a[3] = __float_as_uint(a23.y);
            #pragma unroll
            for (int nt = 0; nt < 4; nt++) {
                int dr = (nhalf + nt * 8 + g) * SP;
                float2 bv = *(const float2*)&sV[dr + o];
                mma8(oacc[nt], a, __float_as_uint(bv.x), __float_as_uint(bv.y));
            }
        }
        __syncthreads();   // protect buf before next iter overwrites
        buf ^= 1;
    }

    // write ctx packed (O-GEMM reads packed k)
    float* Cb = g_C + base;
    #pragma unroll
    for (int nt = 0; nt < 4; nt++) {
        int cb = nhalf + nt * 8;
        size_t r0 = (size_t)(q0 + mrow + g) * HH;
        size_t r1 = (size_t)(q0 + mrow + g + 8) * HH;
        Cb[r0 + cb + sl0] = tfr(oacc[nt][0]);
        Cb[r0 + cb + sl1] = tfr(oacc[nt][1]);
        Cb[r1 + cb + sl0] = tfr(oacc[nt][2]);
        Cb[r1 + cb + sl1] = tfr(oacc[nt][3]);
    }
}

// ---------------------------------------------------------------------------
extern "C" void kernel_launch(void* const* d_in, const int* in_sizes, int n_in,
                              void* d_out, int out_size) {
    const float* x  = (const float*)d_in[0];
    const float* Wq = (const float*)d_in[1];
    const float* bq = (const float*)d_in[2];
    const float* Wk = (const float*)d_in[3];
    const float* bk = (const float*)d_in[4];
    const float* Wv = (const float*)d_in[5];
    const float* bv = (const float*)d_in[6];
    const float* Wo = (const float*)d_in[7];
    const float* bo = (const float*)d_in[8];
    float* out = (float*)d_out;

    float *pxhi, *pxlo, *pWdThi, *pWdTlo, *pWvT, *pWoT, *pbd, *pDhi, *pDlo, *pVt, *pC;
    cudaGetSymbolAddress((void**)&pxhi, g_xhi);
    cudaGetSymbolAddress((void**)&pxlo, g_xlo);
    cudaGetSymbolAddress((void**)&pWdThi, g_WdThi);
    cudaGetSymbolAddress((void**)&pWdTlo, g_WdTlo);
    cudaGetSymbolAddress((void**)&pWvT, g_WvT);
    cudaGetSymbolAddress((void**)&pWoT, g_WoT);
    cudaGetSymbolAddress((void**)&pbd, g_bd);
    cudaGetSymbolAddress((void**)&pDhi, g_Dhi);
    cudaGetSymbolAddress((void**)&pDlo, g_Dlo);
    cudaGetSymbolAddress((void**)&pVt, g_Vt);
    cudaGetSymbolAddress((void**)&pC, g_C);

    const int smem_split = 3 * 4 * 128 * GP * sizeof(float);   // 73728
    const int smem_plain = 3 * 2 * 128 * GP * sizeof(float);   // 36864
    const int smem_attn  = 2 * ASTG * sizeof(float);           // 110592
    static bool attr_set = false;
    if (!attr_set) {
        cudaFuncSetAttribute(gemm_split, cudaFuncAttributeMaxDynamicSharedMemorySize, smem_split);
        cudaFuncSetAttribute(gemm_plain<0>, cudaFuncAttributeMaxDynamicSharedMemorySize, smem_plain);
        cudaFuncSetAttribute(gemm_plain<1>, cudaFuncAttributeMaxDynamicSharedMemorySize, smem_plain);
        cudaFuncSetAttribute(attn_mma, cudaFuncAttributeMaxDynamicSharedMemorySize, smem_attn);
        attr_set = true;
    }

    prep_x<<<MT*HH/256, 256>>>(x, bq, bk);
    prep_w<<<dim3(32, 32, 3), 256>>>(Wq, Wk, Wv, Wo);

    dim3 gg(HH/128, MT/128);  // (8, 32)
    gemm_split<<<gg, 256, smem_split>>>(pxhi, pxlo, pWdThi, pWdTlo, pbd, pDhi, pDlo);
    gemm_plain<1><<<gg, 256, smem_plain>>>(pxhi, pWvT, bv, pVt);

    attn_mma<<<dim3(SS/64, BB*NHH), 256, smem_attn>>>();

    gemm_plain<0><<<gg, 256, smem_plain>>>(pC, pWoT, bo, out);
}

// round 6
// speedup vs baseline: 1.1538x; 1.1538x over previous
#include <cuda_runtime.h>
#include <cstdint>

#define HH  1024
#define BB  2
#define SS  2048
#define NHH 16
#define HDD 64
#define MT  (BB*SS)   // 4096

// ---------------- scratch globals (allocation-free) ----------------
__device__ __align__(128) float g_xhi[MT*HH];
__device__ __align__(128) float g_xlo[MT*HH];
__device__ __align__(128) float g_WdThi[HH*HH];   // (Wq-Wk)^T hi, tf32-rounded
__device__ __align__(128) float g_WdTlo[HH*HH];
__device__ __align__(128) float g_WvT[HH*HH];     // Wv^T tf32-rounded
__device__ __align__(128) float g_WoT[HH*HH];     // Wo^T tf32-rounded
__device__ __align__(128) float g_bd[HH];
__device__ __align__(128) float g_Dhi[MT*HH];     // tf32(D)
__device__ __align__(128) float g_Dlo[MT*HH];     // tf32(D - tf32(D))
__device__ __align__(128) float g_V[MT*HH];       // tf32-rounded V (bias incl.)
__device__ __align__(128) float g_C[MT*HH];       // tf32-rounded attention ctx

// ---------------- helpers ----------------
__device__ __forceinline__ float tfr(float x) {
    uint32_t r;
    asm("cvt.rna.tf32.f32 %0, %1;" : "=r"(r) : "f"(x));
    return __uint_as_float(r);
}
__device__ __forceinline__ void cp16(float* s, const float* g) {
    uint32_t sa = (uint32_t)__cvta_generic_to_shared(s);
    asm volatile("cp.async.cg.shared.global [%0], [%1], 16;" :: "r"(sa), "l"(g));
}
__device__ __forceinline__ void cp_commit() { asm volatile("cp.async.commit_group;"); }
template<int N> __device__ __forceinline__ void cp_wait() {
    asm volatile("cp.async.wait_group %0;" :: "n"(N));
}
__device__ __forceinline__ void mma8(float* d, const uint32_t* a, uint32_t b0, uint32_t b1) {
    asm volatile(
        "mma.sync.aligned.m16n8k8.row.col.f32.tf32.tf32.f32 "
        "{%0,%1,%2,%3},{%4,%5,%6,%7},{%8,%9},{%0,%1,%2,%3};"
        : "+f"(d[0]), "+f"(d[1]), "+f"(d[2]), "+f"(d[3])
        : "r"(a[0]), "r"(a[1]), "r"(a[2]), "r"(a[3]), "r"(b0), "r"(b1));
}

// ---------------- prep: x -> hi/lo planes; bd = bq-bk ----------------
__global__ void prep_x(const float* __restrict__ x,
                       const float* __restrict__ bq, const float* __restrict__ bk) {
    int i = blockIdx.x * 256 + threadIdx.x;
    float v = x[i];
    float hi = tfr(v);
    g_xhi[i] = hi;
    g_xlo[i] = tfr(v - hi);
    if (i < HH) g_bd[i] = bq[i] - bk[i];
}

// ---------------- prep: transpose + tf32-convert weights ----------------
__global__ void prep_w(const float* __restrict__ Wq, const float* __restrict__ Wk,
                       const float* __restrict__ Wv, const float* __restrict__ Wo) {
    __shared__ float t0[32][33];
    __shared__ float t1[32][33];
    const int z = blockIdx.z;
    const int c0 = blockIdx.x * 32, r0 = blockIdx.y * 32;
    const int tx = threadIdx.x & 31, ty = threadIdx.x >> 5;
    #pragma unroll
    for (int rr = ty; rr < 32; rr += 8) {
        int idx = (r0 + rr) * HH + c0 + tx;
        if (z == 0) {
            float v = Wq[idx] - Wk[idx];
            float hi = tfr(v);
            t0[rr][tx] = hi;
            t1[rr][tx] = tfr(v - hi);
        } else if (z == 1) t0[rr][tx] = tfr(Wv[idx]);
        else               t0[rr][tx] = tfr(Wo[idx]);
    }
    __syncthreads();
    #pragma unroll
    for (int rr = ty; rr < 32; rr += 8) {
        int odx = (c0 + rr) * HH + r0 + tx;   // transposed
        if (z == 0) { g_WdThi[odx] = t0[tx][rr]; g_WdTlo[odx] = t1[tx][rr]; }
        else if (z == 1) g_WvT[odx] = t0[tx][rr];
        else             g_WoT[odx] = t0[tx][rr];
    }
}

// ---------------- tf32 GEMM (plain): C = A @ BT^T + bias ----------------
#define GP 12
template<bool ROUND>
__global__ __launch_bounds__(256, 2) void gemm_plain(
    const float* __restrict__ A, const float* __restrict__ BT,
    const float* __restrict__ bias, float* __restrict__ C)
{
    extern __shared__ float sm[];
    const int K = HH, N = HH;
    const int tid = threadIdx.x, w = tid >> 5, lane = tid & 31;
    const int g = lane >> 2, t = lane & 3;
    const int wm = (w & 3) * 32, wn = (w >> 2) * 64;
    const int rowBase = blockIdx.y * 128, colBase = blockIdx.x * 128;
    const int lr = tid >> 1, lc = (tid & 1) * 4;

    const float* pA = A  + (size_t)(rowBase + lr) * K + lc;
    const float* pB = BT + (size_t)(colBase + lr) * K + lc;

    float acc[2][8][4];
    #pragma unroll
    for (int mt = 0; mt < 2; mt++)
        #pragma unroll
        for (int nt = 0; nt < 8; nt++)
            #pragma unroll
            for (int q = 0; q < 4; q++) acc[mt][nt][q] = 0.f;

    const int NIT = K / 8;
    const int off = lr * GP + lc;
    auto issue = [&](int it, int s) {
        float* base = sm + s * 2 * 128 * GP;
        cp16(base + off,          pA + it * 8);
        cp16(base + 128*GP + off, pB + it * 8);
    };
    issue(0, 0); cp_commit();
    issue(1, 1); cp_commit();

    for (int i = 0; i < NIT; i++) {
        cp_wait<1>();
        __syncthreads();
        const float* base = sm + (i % 3) * 2 * 128 * GP;
        const float* sA = base;
        const float* sB = base + 128 * GP;
        uint32_t a[2][4];
        #pragma unroll
        for (int mt = 0; mt < 2; mt++) {
            int r = wm + mt * 16 + g;
            a[mt][0] = __float_as_uint(sA[r * GP + t]);
            a[mt][1] = __float_as_uint(sA[(r + 8) * GP + t]);
            a[mt][2] = __float_as_uint(sA[r * GP + t + 4]);
            a[mt][3] = __float_as_uint(sA[(r + 8) * GP + t + 4]);
        }
        #pragma unroll
        for (int nt = 0; nt < 8; nt++) {
            int c = wn + nt * 8 + g;
            uint32_t b0 = __float_as_uint(sB[c * GP + t]);
            uint32_t b1 = __float_as_uint(sB[c * GP + t + 4]);
            mma8(acc[0][nt], a[0], b0, b1);
            mma8(acc[1][nt], a[1], b0, b1);
        }
        if (i + 2 < NIT) issue(i + 2, (i + 2) % 3);
        cp_commit();
    }

    #pragma unroll
    for (int mt = 0; mt < 2; mt++)
        #pragma unroll
        for (int nt = 0; nt < 8; nt++) {
            int row = rowBase + wm + mt * 16 + g;
            int col = colBase + wn + nt * 8 + 2 * t;
            float2 bb = *(const float2*)(bias + col);
            float v00 = acc[mt][nt][0] + bb.x, v01 = acc[mt][nt][1] + bb.y;
            float v10 = acc[mt][nt][2] + bb.x, v11 = acc[mt][nt][3] + bb.y;
            if (ROUND) { v00 = tfr(v00); v01 = tfr(v01); v10 = tfr(v10); v11 = tfr(v11); }
            *(float2*)(C + (size_t)row * N + col)       = make_float2(v00, v01);
            *(float2*)(C + (size_t)(row + 8) * N + col) = make_float2(v10, v11);
        }
}

// ---------------- tf32x2 split GEMM for D; writes hi/lo planes ----------------
__global__ __launch_bounds__(256, 2) void gemm_split(
    const float* __restrict__ Ah, const float* __restrict__ Al,
    const float* __restrict__ Bh, const float* __restrict__ Bl,
    const float* __restrict__ bias,
    float* __restrict__ Chi, float* __restrict__ Clo)
{
    extern __shared__ float sm[];
    const int K = HH, N = HH;
    const int tid = threadIdx.x, w = tid >> 5, lane = tid & 31;
    const int g = lane >> 2, t = lane & 3;
    const int wm = (w & 3) * 32, wn = (w >> 2) * 64;
    const int rowBase = blockIdx.y * 128, colBase = blockIdx.x * 128;
    const int lr = tid >> 1, lc = (tid & 1) * 4;

    const float* pAh = Ah + (size_t)(rowBase + lr) * K + lc;
    const float* pAl = Al + (size_t)(rowBase + lr) * K + lc;
    const float* pBh = Bh + (size_t)(colBase + lr) * K + lc;
    const float* pBl = Bl + (size_t)(colBase + lr) * K + lc;

    float acc[2][8][4];
    #pragma unroll
    for (int mt = 0; mt < 2; mt++)
        #pragma unroll
        for (int nt = 0; nt < 8; nt++)
            #pragma unroll
            for (int q = 0; q < 4; q++) acc[mt][nt][q] = 0.f;

    const int NIT = K / 8;
    const int off = lr * GP + lc;
    auto issue = [&](int it, int s) {
        float* base = sm + s * 4 * 128 * GP;
        cp16(base + off,            pAh + it * 8);
        cp16(base + 128*GP   + off, pAl + it * 8);
        cp16(base + 2*128*GP + off, pBh + it * 8);
        cp16(base + 3*128*GP + off, pBl + it * 8);
    };
    issue(0, 0); cp_commit();
    issue(1, 1); cp_commit();

    for (int i = 0; i < NIT; i++) {
        cp_wait<1>();
        __syncthreads();
        const float* base = sm + (i % 3) * 4 * 128 * GP;
        const float* sAh = base;
        const float* sAl = base + 128 * GP;
        const float* sBh = base + 2 * 128 * GP;
        const float* sBl = base + 3 * 128 * GP;
        uint32_t ah[2][4], al[2][4];
        #pragma unroll
        for (int mt = 0; mt < 2; mt++) {
            int r = wm + mt * 16 + g;
            ah[mt][0] = __float_as_uint(sAh[r * GP + t]);
            ah[mt][1] = __float_as_uint(sAh[(r + 8) * GP + t]);
            ah[mt][2] = __float_as_uint(sAh[r * GP + t + 4]);
            ah[mt][3] = __float_as_uint(sAh[(r + 8) * GP + t + 4]);
            al[mt][0] = __float_as_uint(sAl[r * GP + t]);
            al[mt][1] = __float_as_uint(sAl[(r + 8) * GP + t]);
            al[mt][2] = __float_as_uint(sAl[r * GP + t + 4]);
            al[mt][3] = __float_as_uint(sAl[(r + 8) * GP + t + 4]);
        }
        #pragma unroll
        for (int nt = 0; nt < 8; nt++) {
            int c = wn + nt * 8 + g;
            uint32_t bh0 = __float_as_uint(sBh[c * GP + t]);
            uint32_t bh1 = __float_as_uint(sBh[c * GP + t + 4]);
            uint32_t bl0 = __float_as_uint(sBl[c * GP + t]);
            uint32_t bl1 = __float_as_uint(sBl[c * GP + t + 4]);
            #pragma unroll
            for (int mt = 0; mt < 2; mt++) {
                mma8(acc[mt][nt], ah[mt], bh0, bh1);
                mma8(acc[mt][nt], ah[mt], bl0, bl1);
                mma8(acc[mt][nt], al[mt], bh0, bh1);
            }
        }
        if (i + 2 < NIT) issue(i + 2, (i + 2) % 3);
        cp_commit();
    }

    #pragma unroll
    for (int mt = 0; mt < 2; mt++)
        #pragma unroll
        for (int nt = 0; nt < 8; nt++) {
            int row = rowBase + wm + mt * 16 + g;
            int col = colBase + wn + nt * 8 + 2 * t;
            float2 bb = *(const float2*)(bias + col);
            float v00 = acc[mt][nt][0] + bb.x, v01 = acc[mt][nt][1] + bb.y;
            float v10 = acc[mt][nt][2] + bb.x, v11 = acc[mt][nt][3] + bb.y;
            float h00 = tfr(v00), h01 = tfr(v01), h10 = tfr(v10), h11 = tfr(v11);
            size_t r0 = (size_t)row * N, r1 = (size_t)(row + 8) * N;
            *(float2*)(Chi + r0 + col) = make_float2(h00, h01);
            *(float2*)(Chi + r1 + col) = make_float2(h10, h11);
            *(float2*)(Clo + r0 + col) = make_float2(tfr(v00 - h00), tfr(v01 - h01));
            *(float2*)(Clo + r1 + col) = make_float2(tfr(v10 - h10), tfr(v11 - h11));
        }
}

// ---------------- attention: 128-row q-tile, 512 threads, 16 warps ----------------
// warp w: rows (w&7)*16 .. +15 of the 128-q block; cols (w>>3)*32 .. +31 of 64.
// Dq-hi fragments in registers; Dq-lo in persistent smem tile; Dk-hi/lo + V
// double-buffered via cp.async. S (128x64) overlays the Kh+Kl stage regions.
#define PK 68
#define PPV 72
#define ASTG (64*PK*2 + 64*PPV)      // 13312 floats per stage
#define DQLO (2*ASTG)                // persistent Dq-lo tile offset (128*PK floats)
__global__ __launch_bounds__(512, 1) void attn_mma() {
    extern __shared__ float sm[];
    const int tid = threadIdx.x, w = tid >> 5, lane = tid & 31;
    const int g = lane >> 2, t = lane & 3;
    const int mrow = (w & 7) * 16, ncol = (w >> 3) * 32;
    const int qt = blockIdx.x, bh = blockIdx.y;
    const int b = bh >> 4, h = bh & 15, q0 = qt * 128;

    const size_t base = (size_t)b * SS * HH + h * HDD;
    const float* Dh = g_Dhi + base;
    const float* Dl = g_Dlo + base;
    const float* Vp = g_V + base;
    float* sDqlo = sm + DQLO;

    // persistent Dq-lo tile: 128 rows x 64 cols
    {
        const int lr2 = tid >> 2, lc2 = (tid & 3) * 16;
        const float* src = Dl + (size_t)(q0 + lr2) * HH + lc2;
        #pragma unroll
        for (int u = 0; u < 16; u += 4)
            *(float4*)&sDqlo[lr2 * PK + lc2 + u] = *(const float4*)(src + u);
    }

    // Dq-hi fragments in registers
    uint32_t qhi[8][4];
    {
        const size_t r0g = (size_t)(q0 + mrow + g) * HH;
        const size_t r1g = (size_t)(q0 + mrow + g + 8) * HH;
        #pragma unroll
        for (int c = 0; c < 8; c++) {
            int o = c * 8;
            qhi[c][0] = __float_as_uint(Dh[r0g + o + t]);
            qhi[c][1] = __float_as_uint(Dh[r1g + o + t]);
            qhi[c][2] = __float_as_uint(Dh[r0g + o + t + 4]);
            qhi[c][3] = __float_as_uint(Dh[r1g + o + t + 4]);
        }
    }

    float oacc[4][4];
    #pragma unroll
    for (int i = 0; i < 4; i++)
        #pragma unroll
        for (int j = 0; j < 4; j++) oacc[i][j] = 0.f;

    const int lr = tid >> 3, lc8 = (tid & 7) * 8;
    auto issue = [&](int jt, int s) {
        float* st = sm + s * ASTG;
        const float* srcH = Dh + (size_t)(jt * 64 + lr) * HH + lc8;
        const float* srcL = Dl + (size_t)(jt * 64 + lr) * HH + lc8;
        const float* srcV = Vp + (size_t)(jt * 64 + lr) * HH + lc8;
        cp16(st + lr * PK + lc8,                srcH);
        cp16(st + lr * PK + lc8 + 4,            srcH + 4);
        cp16(st + 64*PK + lr * PK + lc8,        srcL);
        cp16(st + 64*PK + lr * PK + lc8 + 4,    srcL + 4);
        cp16(st + 2*64*PK + lr * PPV + lc8,     srcV);
        cp16(st + 2*64*PK + lr * PPV + lc8 + 4, srcV + 4);
    };

    const int jt0 = 2 * qt;
    int buf = 0;
    issue(jt0, 0); cp_commit();
    for (int jt = jt0; jt < SS / 64; jt++) {
        if (jt + 1 < SS / 64) { issue(jt + 1, buf ^ 1); cp_commit(); cp_wait<1>(); }
        else cp_wait<0>();
        __syncthreads();   // cp data visible to all; also fences sDqlo/prev-iter reads
        float* st = sm + buf * ASTG;
        float* sKh = st;                        // S (128 x PK) overlays Kh+Kl
        const float* sKl = st + 64 * PK;
        const float* sV  = st + 2 * 64 * PK;
        const int j0 = jt * 64;

        // score = Dq@Dk^T (3-mma tf32x2)
        float sacc[4][4];
        #pragma unroll
        for (int i = 0; i < 4; i++)
            #pragma unroll
            for (int j = 0; j < 4; j++) sacc[i][j] = 0.f;

        #pragma unroll
        for (int c = 0; c < 8; c++) {
            int o = c * 8;
            uint32_t ql[4];
            ql[0] = __float_as_uint(sDqlo[(mrow + g) * PK + o + t]);
            ql[1] = __float_as_uint(sDqlo[(mrow + g + 8) * PK + o + t]);
            ql[2] = __float_as_uint(sDqlo[(mrow + g) * PK + o + t + 4]);
            ql[3] = __float_as_uint(sDqlo[(mrow + g + 8) * PK + o + t + 4]);
            #pragma unroll
            for (int nt = 0; nt < 4; nt++) {
                int jr = (ncol + nt * 8 + g) * PK;
                uint32_t bh0 = __float_as_uint(sKh[jr + o + t]);
                uint32_t bh1 = __float_as_uint(sKh[jr + o + t + 4]);
                uint32_t bl0 = __float_as_uint(sKl[jr + o + t]);
                uint32_t bl1 = __float_as_uint(sKl[jr + o + t + 4]);
                mma8(sacc[nt], qhi[c], bh0, bh1);
                mma8(sacc[nt], qhi[c], bl0, bl1);
                mma8(sacc[nt], ql,     bh0, bh1);
            }
        }

        // mask (strict upper) + exp + pre-round
        const int r0 = q0 + mrow + g;
        #pragma unroll
        for (int nt = 0; nt < 4; nt++) {
            int colb = j0 + ncol + nt * 8 + 2 * t;
            sacc[nt][0] = (colb     > r0    ) ? tfr(__expf(-0.5f * sacc[nt][0])) : 0.f;
            sacc[nt][1] = (colb + 1 > r0    ) ? tfr(__expf(-0.5f * sacc[nt][1])) : 0.f;
            sacc[nt][2] = (colb     > r0 + 8) ? tfr(__expf(-0.5f * sacc[nt][2])) : 0.f;
            sacc[nt][3] = (colb + 1 > r0 + 8) ? tfr(__expf(-0.5f * sacc[nt][3])) : 0.f;
        }

        __syncthreads();   // all score reads of Kh/Kl complete
        #pragma unroll
        for (int nt = 0; nt < 4; nt++) {
            int cb = ncol + nt * 8 + 2 * t;
            *(float2*)&sKh[(mrow + g) * PK + cb]     = make_float2(sacc[nt][0], sacc[nt][1]);
            *(float2*)&sKh[(mrow + g + 8) * PK + cb] = make_float2(sacc[nt][2], sacc[nt][3]);
        }
        __syncthreads();

        // PV: oacc += S @ V  (plain tf32)
        #pragma unroll
        for (int c = 0; c < 8; c++) {
            int k = c * 8;
            uint32_t a[4];
            a[0] = __float_as_uint(sKh[(mrow + g) * PK + k + t]);
            a[1] = __float_as_uint(sKh[(mrow + g + 8) * PK + k + t]);
            a[2] = __float_as_uint(sKh[(mrow + g) * PK + k + t + 4]);
            a[3] = __float_as_uint(sKh[(mrow + g + 8) * PK + k + t + 4]);
            #pragma unroll
            for (int nt = 0; nt < 4; nt++) {
                int dbc = ncol + nt * 8;
                uint32_t b0 = __float_as_uint(sV[(k + t) * PPV + dbc + g]);
                uint32_t b1 = __float_as_uint(sV[(k + t + 4) * PPV + dbc + g]);
                mma8(oacc[nt], a, b0, b1);
            }
        }
        __syncthreads();   // PV reads done before next iter reuses this buffer
        buf ^= 1;
    }

    // write ctx pre-rounded (O GEMM consumes tf32 directly)
    float* Cb = g_C + base;
    #pragma unroll
    for (int nt = 0; nt < 4; nt++) {
        int col = ncol + nt * 8 + 2 * t;
        *(float2*)(Cb + (size_t)(q0 + mrow + g) * HH + col) =
            make_float2(tfr(oacc[nt][0]), tfr(oacc[nt][1]));
        *(float2*)(Cb + (size_t)(q0 + mrow + g + 8) * HH + col) =
            make_float2(tfr(oacc[nt][2]), tfr(oacc[nt][3]));
    }
}

// ---------------------------------------------------------------------------
extern "C" void kernel_launch(void* const* d_in, const int* in_sizes, int n_in,
                              void* d_out, int out_size) {
    const float* x  = (const float*)d_in[0];
    const float* Wq = (const float*)d_in[1];
    const float* bq = (const float*)d_in[2];
    const float* Wk = (const float*)d_in[3];
    const float* bk = (const float*)d_in[4];
    const float* Wv = (const float*)d_in[5];
    const float* bv = (const float*)d_in[6];
    const float* Wo = (const float*)d_in[7];
    const float* bo = (const float*)d_in[8];
    float* out = (float*)d_out;

    float *pxhi, *pxlo, *pWdThi, *pWdTlo, *pWvT, *pWoT, *pbd, *pDhi, *pDlo, *pV, *pC;
    cudaGetSymbolAddress((void**)&pxhi, g_xhi);
    cudaGetSymbolAddress((void**)&pxlo, g_xlo);
    cudaGetSymbolAddress((void**)&pWdThi, g_WdThi);
    cudaGetSymbolAddress((void**)&pWdTlo, g_WdTlo);
    cudaGetSymbolAddress((void**)&pWvT, g_WvT);
    cudaGetSymbolAddress((void**)&pWoT, g_WoT);
    cudaGetSymbolAddress((void**)&pbd, g_bd);
    cudaGetSymbolAddress((void**)&pDhi, g_Dhi);
    cudaGetSymbolAddress((void**)&pDlo, g_Dlo);
    cudaGetSymbolAddress((void**)&pV, g_V);
    cudaGetSymbolAddress((void**)&pC, g_C);

    const int smem_split = 3 * 4 * 128 * GP * sizeof(float);          // 73728
    const int smem_plain = 3 * 2 * 128 * GP * sizeof(float);          // 36864
    const int smem_attn  = (2 * ASTG + 128 * PK) * sizeof(float);     // 141312
    static bool attr_set = false;
    if (!attr_set) {
        cudaFuncSetAttribute(gemm_split, cudaFuncAttributeMaxDynamicSharedMemorySize, smem_split);
        cudaFuncSetAttribute(gemm_plain<true>,  cudaFuncAttributeMaxDynamicSharedMemorySize, smem_plain);
        cudaFuncSetAttribute(gemm_plain<false>, cudaFuncAttributeMaxDynamicSharedMemorySize, smem_plain);
        cudaFuncSetAttribute(attn_mma, cudaFuncAttributeMaxDynamicSharedMemorySize, smem_attn);
        attr_set = true;
    }

    prep_x<<<MT*HH/256, 256>>>(x, bq, bk);
    prep_w<<<dim3(32, 32, 3), 256>>>(Wq, Wk, Wv, Wo);

    dim3 gg(HH/128, MT/128);  // (8, 32)
    gemm_split<<<gg, 256, smem_split>>>(pxhi, pxlo, pWdThi, pWdTlo, pbd, pDhi, pDlo);
    gemm_plain<true><<<gg, 256, smem_plain>>>(pxhi, pWvT, bv, pV);

    attn_mma<<<dim3(SS/128, BB*NHH), 512, smem_attn>>>();

    gemm_plain<false><<<gg, 256, smem_plain>>>(pC, pWoT, bo, out);
}